// round 9
// baseline (speedup 1.0000x reference)
#include <cuda_runtime.h>
#include <math.h>
#include <cstdint>

#define BB 64
#define LL 2048
#define HH 256
#define BLH (BB*LL*HH)

// Scratch (device globals: allocation-free per harness rules)
__device__ float g_Z[BLH];     // input-transform term per (b,t,h)
__device__ float g_H0[BLH];    // layer-0 hidden states

// ---------------------------------------------------------------------------
// PTX helpers
__device__ __forceinline__ uint32_t s2u(const void* p) {
    uint32_t a;
    asm("{ .reg .u64 t; cvta.to.shared.u64 t, %1; cvt.u32.u64 %0, t; }"
        : "=r"(a) : "l"(p));
    return a;
}
__device__ __forceinline__ uint32_t mapa_u32(uint32_t addr, uint32_t rank) {
    uint32_t r;
    asm("mapa.shared::cluster.u32 %0, %1, %2;" : "=r"(r) : "r"(addr), "r"(rank));
    return r;
}
__device__ __forceinline__ void mbar_init(uint32_t mbar, uint32_t count) {
    asm volatile("mbarrier.init.shared::cta.b64 [%0], %1;" :: "r"(mbar), "r"(count) : "memory");
}
__device__ __forceinline__ void st_remote_f32(uint32_t raddr, float v) {
    asm volatile("st.shared::cluster.f32 [%0], %1;" :: "r"(raddr), "f"(v) : "memory");
}
// Cluster-scope release arrive on peer's mbarrier (orders prior cluster stores).
__device__ __forceinline__ void mbar_arrive_remote_release(uint32_t raddr) {
    asm volatile("mbarrier.arrive.release.cluster.shared::cluster.b64 _, [%0];"
                 :: "r"(raddr) : "memory");
}
__device__ __forceinline__ void mbar_wait_parity(uint32_t mbar, uint32_t parity) {
    uint32_t done;
    asm volatile(
        "{\n\t.reg .pred p;\n\t"
        "mbarrier.try_wait.parity.acquire.cluster.shared::cta.b64 p, [%1], %2;\n\t"
        "selp.b32 %0, 1, 0, p;\n\t}"
        : "=r"(done) : "r"(mbar), "r"(parity) : "memory");
    if (!done) {
        asm volatile(
            "{\n\t.reg .pred P1;\n\t"
            "WL_%=:\n\t"
            "mbarrier.try_wait.parity.acquire.cluster.shared::cta.b64 P1, [%0], %1, 0x989680;\n\t"
            "@P1 bra.uni WD_%=;\n\t"
            "bra.uni WL_%=;\n\t"
            "WD_%=:\n\t}"
            :: "r"(mbar), "r"(parity) : "memory");
    }
}
__device__ __forceinline__ void cluster_sync() {
    asm volatile("barrier.cluster.arrive.aligned;" ::: "memory");
    asm volatile("barrier.cluster.wait.aligned;" ::: "memory");
}

// ---- packed f32x2 ----
typedef unsigned long long ull;
__device__ __forceinline__ ull pk2(float lo, float hi) {
    ull r;
    asm("mov.b64 %0, {%1, %2};" : "=l"(r) : "f"(lo), "f"(hi));
    return r;
}
__device__ __forceinline__ void upk2(float& lo, float& hi, ull v) {
    asm("mov.b64 {%0, %1}, %2;" : "=f"(lo), "=f"(hi) : "l"(v));
}
__device__ __forceinline__ void ffma2(ull& d, ull a, ull b) {
    asm("fma.rn.f32x2 %0, %1, %2, %0;" : "+l"(d) : "l"(a), "l"(b));
}

// ---------------------------------------------------------------------------
// GEMM + bias: Out[r][j] = sum_k In[r][k]*W[k][j] + bi[j] + bh[j]
// M = 131072, N = K = 256. Tile 128x128x8, 256 threads, 8x8/thread, FFMA2.
__global__ __launch_bounds__(256) void gemm_bias(
        const float* __restrict__ In, const float* __restrict__ W,
        const float* __restrict__ bi, const float* __restrict__ bh,
        float* __restrict__ Out)
{
    __shared__ float As[8][128];
    __shared__ float Bs[8][128];
    const int tid  = threadIdx.x;
    const int mblk = blockIdx.x * 128;
    const int nblk = blockIdx.y * 128;
    const int tx = tid & 15, ty = tid >> 4;

    const int ar = tid >> 1;
    const int ak = (tid & 1) * 4;
    const int bk = tid >> 5;
    const int bc = (tid & 31) * 4;

    const float* Arow = In + (size_t)(mblk + ar) * HH;
    float4 a_next = *(const float4*)(Arow + ak);
    float4 b_next = *(const float4*)(W + (size_t)bk * HH + nblk + bc);

    ull acc2[8][4];   // [row i][col pair j2] -> cols tx*8+2*j2, +1
#pragma unroll
    for (int i = 0; i < 8; i++)
#pragma unroll
        for (int j = 0; j < 4; j++) acc2[i][j] = 0ull;

    for (int kt = 0; kt < 32; kt++) {
        As[ak + 0][ar] = a_next.x;
        As[ak + 1][ar] = a_next.y;
        As[ak + 2][ar] = a_next.z;
        As[ak + 3][ar] = a_next.w;
        *(float4*)&Bs[bk][bc] = b_next;
        __syncthreads();
        if (kt < 31) {
            a_next = *(const float4*)(Arow + (kt + 1) * 8 + ak);
            b_next = *(const float4*)(W + (size_t)((kt + 1) * 8 + bk) * HH + nblk + bc);
        }
#pragma unroll
        for (int kk = 0; kk < 8; kk++) {
            float a[8];
            *(float4*)&a[0] = *(const float4*)&As[kk][ty * 8];
            *(float4*)&a[4] = *(const float4*)&As[kk][ty * 8 + 4];
            float4 b0 = *(const float4*)&Bs[kk][tx * 8];
            float4 b1 = *(const float4*)&Bs[kk][tx * 8 + 4];
            ull bp[4] = { pk2(b0.x, b0.y), pk2(b0.z, b0.w),
                          pk2(b1.x, b1.y), pk2(b1.z, b1.w) };
#pragma unroll
            for (int i = 0; i < 8; i++) {
                const ull ad = pk2(a[i], a[i]);
#pragma unroll
                for (int j = 0; j < 4; j++) ffma2(acc2[i][j], ad, bp[j]);
            }
        }
        __syncthreads();
    }

#pragma unroll
    for (int i = 0; i < 8; i++) {
        const size_t r = (size_t)(mblk + ty * 8 + i);
#pragma unroll
        for (int j2 = 0; j2 < 4; j2 += 2) {
            const int c = nblk + tx * 8 + j2 * 2;
            float4 v;
            upk2(v.x, v.y, acc2[i][j2 + 0]);
            upk2(v.z, v.w, acc2[i][j2 + 1]);
            v.x += bi[c + 0] + bh[c + 0];
            v.y += bi[c + 1] + bh[c + 1];
            v.z += bi[c + 2] + bh[c + 2];
            v.w += bi[c + 3] + bh[c + 3];
            *(float4*)(Out + r * HH + c) = v;
        }
    }
}

// ---------------------------------------------------------------------------
// Recurrence pass, v2: warp-private columns, FFMA2 dot products, no smem
// reduction, one __syncthreads per step.
//   Cluster of 2 CTAs per batch; CTA rank r owns cols [r*128, +128).
//   Warp w owns 16 cols; lane l computes col (l&15) over k-quarter (l>>4)
//   of each 128-wide half (64 k's own + 64 k's peer = 128 FLOP-pairs via
//   64 FFMA2). shfl.bfly(16) merges the two k-quarters. Exchange: remote
//   stores into peer recvbuf + release.cluster arrive per warp (count=8),
//   double-buffered; acquire try_wait on consumer side. Own-half matvec
//   runs before the wait to hide DSMEM latency.
__global__ __launch_bounds__(256, 1) __cluster_dims__(2, 1, 1)
void rnn_pass(
        const float* __restrict__ Z,    // [B,L,H]
        const float* __restrict__ Wh,   // [H,H]
        const float* __restrict__ h0,   // [B,H]
        float* __restrict__ Out,        // [B,L,H]
        float* __restrict__ hfinal)     // [B,H] or null
{
    const int b     = blockIdx.x >> 1;
    const int half  = blockIdx.x & 1;            // == cluster rank
    const int jbase = half << 7;
    const int peerbase = 128 - jbase;
    const int tid  = threadIdx.x;
    const int w    = tid >> 5;
    const int lane = tid & 31;
    const int cl   = (w << 4) + (lane & 15);     // col within own block (0..127)
    const int kq   = lane >> 4;                  // k-quarter selector (0/1)
    const int colabs = jbase + cl;

    __shared__ float sh_h[256];                  // own half live; peer half only at t=0
    __shared__ float recvbuf[2][128];            // peer halves, double-buffered
    __shared__ uint64_t mbar[2];

    const uint32_t mbar0 = s2u(&mbar[0]);
    const uint32_t mbar1 = s2u(&mbar[1]);
    const uint32_t rb0   = s2u(&recvbuf[0][0]);
    const uint32_t rb1   = s2u(&recvbuf[1][0]);
    const uint32_t prank = (uint32_t)(half ^ 1);
    const uint32_t p_rb[2]   = { mapa_u32(rb0 + (uint32_t)cl * 4u, prank),
                                 mapa_u32(rb1 + (uint32_t)cl * 4u, prank) };
    const uint32_t p_mbar[2] = { mapa_u32(mbar0, prank), mapa_u32(mbar1, prank) };
    const uint32_t l_mbar[2] = { mbar0, mbar1 };

    if (tid == 0) { mbar_init(mbar0, 8); mbar_init(mbar1, 8); }   // 8 producer warps

    // Weights: 64 f32x2 pairs (k-adjacent) for this thread's (col, k-quarter).
    ull wown[32], wpeer[32];
#pragma unroll
    for (int m = 0; m < 32; m++) {
        const int k0 = jbase + kq * 64 + 2 * m;
        wown[m] = pk2(Wh[(size_t)k0 * HH + colabs], Wh[(size_t)(k0 + 1) * HH + colabs]);
    }
#pragma unroll
    for (int m = 0; m < 32; m++) {
        const int k0 = peerbase + kq * 64 + 2 * m;
        wpeer[m] = pk2(Wh[(size_t)k0 * HH + colabs], Wh[(size_t)(k0 + 1) * HH + colabs]);
    }

    if (tid < 256) sh_h[tid] = h0[b * HH + tid];
    __syncthreads();
    cluster_sync();   // mbarrier init visible cluster-wide before any remote arrive

    // Z prefetch (one step ahead); valid for lanes 0-15 only.
    float zv = (lane < 16) ? Z[((size_t)b * LL + 0) * HH + colabs] : 0.f;

    for (int t = 0; t < LL; t++) {
        float zv_next = 0.f;
        if (t + 1 < LL && lane < 16)
            zv_next = Z[((size_t)b * LL + (t + 1)) * HH + colabs];

        ull a0 = 0ull, a1 = 0ull, a2 = 0ull, a3 = 0ull;

        // ---- phase 1: own k-half (local, no wait) ----
        {
            const float4* h4 = (const float4*)(sh_h + jbase + kq * 64);
#pragma unroll
            for (int m = 0; m < 16; m++) {
                const float4 hv4 = h4[m];
                const ull p0 = pk2(hv4.x, hv4.y);
                const ull p1 = pk2(hv4.z, hv4.w);
                if (m & 1) { ffma2(a2, wown[2 * m], p0); ffma2(a3, wown[2 * m + 1], p1); }
                else       { ffma2(a0, wown[2 * m], p0); ffma2(a1, wown[2 * m + 1], p1); }
            }
        }

        // ---- wait for peer half of h_{t-1} ----
        const float4* s4;
        if (t > 0) {
            mbar_wait_parity(l_mbar[(t - 1) & 1], ((t - 1) >> 1) & 1);
            s4 = (const float4*)(&recvbuf[(t - 1) & 1][0]) + kq * 16;
        } else {
            s4 = (const float4*)(sh_h + peerbase) + kq * 16;
        }

        // ---- phase 2: peer k-half ----
        {
#pragma unroll
            for (int m = 0; m < 16; m++) {
                const float4 hv4 = s4[m];
                const ull p0 = pk2(hv4.x, hv4.y);
                const ull p1 = pk2(hv4.z, hv4.w);
                if (m & 1) { ffma2(a2, wpeer[2 * m], p0); ffma2(a3, wpeer[2 * m + 1], p1); }
                else       { ffma2(a0, wpeer[2 * m], p0); ffma2(a1, wpeer[2 * m + 1], p1); }
            }
        }

        // ---- merge accumulators + cross-quarter shuffle + tanh + publish ----
        float l0, h0v, l1, h1v, l2, h2v, l3, h3v;
        upk2(l0, h0v, a0); upk2(l1, h1v, a1); upk2(l2, h2v, a2); upk2(l3, h3v, a3);
        float s = ((l0 + l1) + (l2 + l3)) + ((h0v + h1v) + (h2v + h3v));
        s += __shfl_xor_sync(0xffffffffu, s, 16);
        s += zv;
        const float hv = tanhf(s);

        if (lane < 16) {
            sh_h[colabs] = hv;                                    // own half for t+1
            if (t < LL - 1) st_remote_f32(p_rb[t & 1], hv);       // push to peer buf
            Out[((size_t)b * LL + t) * HH + colabs] = hv;         // result (off chain)
        }
        __syncwarp();                                             // warp stores ordered
        if (t < LL - 1 && lane == 0)
            mbar_arrive_remote_release(p_mbar[t & 1]);            // RELEASE.CLUSTER
        zv = zv_next;
        __syncthreads();   // sh_h own-half ready for all warps' next phase 1
    }

    if (hfinal && lane < 16)
        hfinal[b * HH + colabs] = sh_h[colabs];

    cluster_sync();   // no CTA exits while peer stores may be in flight
}

// ---------------------------------------------------------------------------
extern "C" void kernel_launch(void* const* d_in, const int* in_sizes, int n_in,
                              void* d_out, int out_size) {
    const float* x  = (const float*)d_in[0];   // [B,L,H]
    const float* h0 = (const float*)d_in[1];   // [NL,B,H]
    const float* WI = (const float*)d_in[2];   // [NL,H,H]
    const float* BI = (const float*)d_in[3];   // [NL,H]
    const float* WH = (const float*)d_in[4];   // [NL,H,H]
    const float* BH = (const float*)d_in[5];   // [NL,H]
    float* out = (float*)d_out;

    float *gZ = nullptr, *gH0 = nullptr;
    cudaGetSymbolAddress((void**)&gZ, g_Z);
    cudaGetSymbolAddress((void**)&gH0, g_H0);

    const dim3 ggrid(BB * LL / 128, HH / 128);  // (1024, 2)

    const bool haveMain  = (out_size >= BLH);
    const bool haveFinal = (out_size >= BLH + 2 * BB * HH);
    float* out2 = haveMain ? out : gZ;
    float* hf0  = haveFinal ? (out + BLH) : (haveMain ? nullptr : out);
    float* hf1  = haveFinal ? (out + BLH + BB * HH)
                            : (haveMain ? nullptr : out + BB * HH);

    // Phase A: Z0 = X @ WI0 + BI0 + BH0
    gemm_bias<<<ggrid, 256>>>(x, WI, BI, BH, gZ);
    // Phase B: layer-0 recurrence (64 clusters x 2 CTAs)
    rnn_pass<<<2 * BB, 256>>>(gZ, WH, h0, gH0, hf0);
    // Phase C: Z1 = H0 @ WI1 + BI1 + BH1
    gemm_bias<<<ggrid, 256>>>(gH0, WI + HH * HH, BI + HH, BH + HH, gZ);
    // Phase D: layer-1 recurrence -> output
    rnn_pass<<<2 * BB, 256>>>(gZ, WH + HH * HH, h0 + BB * HH, out2, hf1);
}

// round 10
// speedup vs baseline: 1.4540x; 1.4540x over previous
#include <cuda_runtime.h>
#include <math.h>
#include <cstdint>

#define BB 64
#define LL 2048
#define HH 256
#define BLH (BB*LL*HH)

// Scratch (device globals: allocation-free per harness rules)
__device__ float g_Z[BLH];     // input-transform term per (b,t,h)
__device__ float g_H0[BLH];    // layer-0 hidden states

// ---------------------------------------------------------------------------
// PTX helpers (R8-proven set)
__device__ __forceinline__ uint32_t s2u(const void* p) {
    uint32_t a;
    asm("{ .reg .u64 t; cvta.to.shared.u64 t, %1; cvt.u32.u64 %0, t; }"
        : "=r"(a) : "l"(p));
    return a;
}
__device__ __forceinline__ uint32_t mapa_u32(uint32_t addr, uint32_t rank) {
    uint32_t r;
    asm("mapa.shared::cluster.u32 %0, %1, %2;" : "=r"(r) : "r"(addr), "r"(rank));
    return r;
}
__device__ __forceinline__ void mbar_init(uint32_t mbar, uint32_t count) {
    asm volatile("mbarrier.init.shared::cta.b64 [%0], %1;" :: "r"(mbar), "r"(count) : "memory");
}
__device__ __forceinline__ void st_remote_f32(uint32_t raddr, float v) {
    asm volatile("st.shared::cluster.f32 [%0], %1;" :: "r"(raddr), "f"(v) : "memory");
}
// Cluster-scope release arrive on peer's mbarrier (orders prior cluster stores).
__device__ __forceinline__ void mbar_arrive_remote_release(uint32_t raddr) {
    asm volatile("mbarrier.arrive.release.cluster.shared::cluster.b64 _, [%0];"
                 :: "r"(raddr) : "memory");
}
__device__ __forceinline__ void mbar_wait_parity(uint32_t mbar, uint32_t parity) {
    uint32_t done;
    asm volatile(
        "{\n\t.reg .pred p;\n\t"
        "mbarrier.try_wait.parity.acquire.cluster.shared::cta.b64 p, [%1], %2;\n\t"
        "selp.b32 %0, 1, 0, p;\n\t}"
        : "=r"(done) : "r"(mbar), "r"(parity) : "memory");
    if (!done) {
        asm volatile(
            "{\n\t.reg .pred P1;\n\t"
            "WL_%=:\n\t"
            "mbarrier.try_wait.parity.acquire.cluster.shared::cta.b64 P1, [%0], %1, 0x989680;\n\t"
            "@P1 bra.uni WD_%=;\n\t"
            "bra.uni WL_%=;\n\t"
            "WD_%=:\n\t}"
            :: "r"(mbar), "r"(parity) : "memory");
    }
}
__device__ __forceinline__ void cluster_sync() {
    asm volatile("barrier.cluster.arrive.aligned;" ::: "memory");
    asm volatile("barrier.cluster.wait.aligned;" ::: "memory");
}

// ---------------------------------------------------------------------------
// GEMM + bias (R8-proven scalar version): Out[r][j] = In[r]·W[:,j] + bi[j] + bh[j]
// M = 131072, N = K = 256. Tile 128x128x8, 256 threads, 8x8/thread.
__global__ __launch_bounds__(256) void gemm_bias(
        const float* __restrict__ In, const float* __restrict__ W,
        const float* __restrict__ bi, const float* __restrict__ bh,
        float* __restrict__ Out)
{
    __shared__ float As[8][128];
    __shared__ float Bs[8][128];
    const int tid  = threadIdx.x;
    const int mblk = blockIdx.x * 128;
    const int nblk = blockIdx.y * 128;
    const int tx = tid & 15, ty = tid >> 4;

    const int ar = tid >> 1;
    const int ak = (tid & 1) * 4;
    const int bk = tid >> 5;
    const int bc = (tid & 31) * 4;

    const float* Arow = In + (size_t)(mblk + ar) * HH;
    float4 a_next = *(const float4*)(Arow + ak);
    float4 b_next = *(const float4*)(W + (size_t)bk * HH + nblk + bc);

    float acc[8][8];
#pragma unroll
    for (int i = 0; i < 8; i++)
#pragma unroll
        for (int j = 0; j < 8; j++) acc[i][j] = 0.f;

    for (int kt = 0; kt < 32; kt++) {
        As[ak + 0][ar] = a_next.x;
        As[ak + 1][ar] = a_next.y;
        As[ak + 2][ar] = a_next.z;
        As[ak + 3][ar] = a_next.w;
        *(float4*)&Bs[bk][bc] = b_next;
        __syncthreads();
        if (kt < 31) {
            a_next = *(const float4*)(Arow + (kt + 1) * 8 + ak);
            b_next = *(const float4*)(W + (size_t)((kt + 1) * 8 + bk) * HH + nblk + bc);
        }
#pragma unroll
        for (int kk = 0; kk < 8; kk++) {
            float a[8], b[8];
            *(float4*)&a[0] = *(const float4*)&As[kk][ty * 8];
            *(float4*)&a[4] = *(const float4*)&As[kk][ty * 8 + 4];
            *(float4*)&b[0] = *(const float4*)&Bs[kk][tx * 8];
            *(float4*)&b[4] = *(const float4*)&Bs[kk][tx * 8 + 4];
#pragma unroll
            for (int i = 0; i < 8; i++)
#pragma unroll
                for (int j = 0; j < 8; j++) acc[i][j] += a[i] * b[j];
        }
        __syncthreads();
    }

#pragma unroll
    for (int i = 0; i < 8; i++) {
        const size_t r = (size_t)(mblk + ty * 8 + i);
#pragma unroll
        for (int j = 0; j < 8; j += 4) {
            const int c = nblk + tx * 8 + j;
            float4 v;
            v.x = acc[i][j + 0] + bi[c + 0] + bh[c + 0];
            v.y = acc[i][j + 1] + bi[c + 1] + bh[c + 1];
            v.z = acc[i][j + 2] + bi[c + 2] + bh[c + 2];
            v.w = acc[i][j + 3] + bi[c + 3] + bh[c + 3];
            *(float4*)(Out + r * HH + c) = v;
        }
    }
}

// ---------------------------------------------------------------------------
// Recurrence pass, 2 batches per cluster (weights shared across batches).
// Cluster c handles batches (2c, 2c+1); CTA rank r owns cols [r*128,+128) of
// BOTH batches. R8-proven exchange: remote stores into peer's double-buffered
// recvbuf + release.cluster arrive per warp (count=8); acquire try_wait on
// consumer. One wait/reduction/barrier pair per step serves both batches.
// Compute mapping (per batch): warp w = k-slice [w*16,+16), lane -> 4 cols.
// Publish mapping: thread tid -> batch (tid>>7), col (tid&127).
__global__ __launch_bounds__(256, 1) __cluster_dims__(2, 1, 1)
void rnn_pass2(
        const float* __restrict__ Z,    // [B,L,H]
        const float* __restrict__ Wh,   // [H,H]
        const float* __restrict__ h0,   // [B,H]
        float* __restrict__ Out,        // [B,L,H]
        float* __restrict__ hfinal)     // [B,H] or null
{
    const int cid   = blockIdx.x >> 1;
    const int half  = blockIdx.x & 1;            // == cluster rank
    const int b0    = cid * 2;                   // batches b0, b0+1
    const int jbase = half << 7;
    const int peerbase = 128 - jbase;
    const int tid  = threadIdx.x;
    const int w    = tid >> 5;
    const int lane = tid & 31;
    const int j0   = jbase + lane * 4;           // compute cols (4)
    const int pb   = tid >> 7;                   // publish batch (0/1)
    const int pcol = tid & 127;                  // publish col within half
    const int pcolabs = jbase + pcol;
    const int pbatch  = b0 + pb;                 // global batch for publish

    __shared__ float sh_h[2][256];               // [batch][h]; own half live
    __shared__ float recvbuf[2][2][128];         // [buf][batch][peer half]
    __shared__ float sacc[2][8 * 128];           // [batch][warp*128+col]
    __shared__ uint64_t mbar[2];

    const uint32_t mbar0 = s2u(&mbar[0]);
    const uint32_t mbar1 = s2u(&mbar[1]);
    const uint32_t rbB   = s2u(&recvbuf[0][0][0]);
    const uint32_t prank = (uint32_t)(half ^ 1);
    // Each thread pushes 1 float/step: recvbuf[buf][pb][pcol] on the peer.
    const uint32_t p_rb[2] = {
        mapa_u32(rbB + (uint32_t)((0 * 2 + pb) * 128 + pcol) * 4u, prank),
        mapa_u32(rbB + (uint32_t)((1 * 2 + pb) * 128 + pcol) * 4u, prank) };
    const uint32_t p_mbar[2] = { mapa_u32(mbar0, prank), mapa_u32(mbar1, prank) };
    const uint32_t l_mbar[2] = { mbar0, mbar1 };

    if (tid == 0) { mbar_init(mbar0, 8); mbar_init(mbar1, 8); }   // 8 producer warps

    // Weight slice (shared by both batches): wreg[0]=own k-half, wreg[1]=peer.
    float4 wreg[2][16];
    const int kb0 = jbase, kb1 = peerbase;
#pragma unroll
    for (int kk = 0; kk < 16; kk++)
        wreg[0][kk] = *(const float4*)(Wh + (size_t)(kb0 + w * 16 + kk) * HH + j0);
#pragma unroll
    for (int kk = 0; kk < 16; kk++)
        wreg[1][kk] = *(const float4*)(Wh + (size_t)(kb1 + w * 16 + kk) * HH + j0);

    sh_h[0][tid] = h0[(b0 + 0) * HH + tid];
    sh_h[1][tid] = h0[(b0 + 1) * HH + tid];
    __syncthreads();
    cluster_sync();   // mbarrier init visible cluster-wide before any remote arrive

    // Z prefetch (one step ahead), one value per thread (its publish column).
    float zv = Z[((size_t)pbatch * LL + 0) * HH + pcolabs];

    for (int t = 0; t < LL; t++) {
        float zv_next = 0.f;
        if (t + 1 < LL)
            zv_next = Z[((size_t)pbatch * LL + (t + 1)) * HH + pcolabs];

        float4 acc0 = make_float4(0.f, 0.f, 0.f, 0.f);
        float4 acc1 = make_float4(0.f, 0.f, 0.f, 0.f);

        // ---- phase 1: own k-half, both batches (local, no wait) ----
        {
            const float4* h4a = (const float4*)(&sh_h[0][kb0 + w * 16]);
            const float4* h4b = (const float4*)(&sh_h[1][kb0 + w * 16]);
            float ha[16], hb[16];
            *(float4*)&ha[0]  = h4a[0]; *(float4*)&ha[4]  = h4a[1];
            *(float4*)&ha[8]  = h4a[2]; *(float4*)&ha[12] = h4a[3];
            *(float4*)&hb[0]  = h4b[0]; *(float4*)&hb[4]  = h4b[1];
            *(float4*)&hb[8]  = h4b[2]; *(float4*)&hb[12] = h4b[3];
#pragma unroll
            for (int kk = 0; kk < 16; kk++) {
                const float4 wv = wreg[0][kk];
                const float va = ha[kk], vb = hb[kk];
                acc0.x += wv.x * va; acc0.y += wv.y * va;
                acc0.z += wv.z * va; acc0.w += wv.w * va;
                acc1.x += wv.x * vb; acc1.y += wv.y * vb;
                acc1.z += wv.z * vb; acc1.w += wv.w * vb;
            }
        }

        // ---- wait for peer halves of h_{t-1} (both batches, one barrier) ----
        const float4 *s4a, *s4b;
        if (t > 0) {
            mbar_wait_parity(l_mbar[(t - 1) & 1], ((t - 1) >> 1) & 1);
            s4a = (const float4*)(&recvbuf[(t - 1) & 1][0][w * 16]);
            s4b = (const float4*)(&recvbuf[(t - 1) & 1][1][w * 16]);
        } else {
            s4a = (const float4*)(&sh_h[0][kb1 + w * 16]);
            s4b = (const float4*)(&sh_h[1][kb1 + w * 16]);
        }

        // ---- phase 2: peer k-half, both batches ----
        {
            float ha[16], hb[16];
            *(float4*)&ha[0]  = s4a[0]; *(float4*)&ha[4]  = s4a[1];
            *(float4*)&ha[8]  = s4a[2]; *(float4*)&ha[12] = s4a[3];
            *(float4*)&hb[0]  = s4b[0]; *(float4*)&hb[4]  = s4b[1];
            *(float4*)&hb[8]  = s4b[2]; *(float4*)&hb[12] = s4b[3];
#pragma unroll
            for (int kk = 0; kk < 16; kk++) {
                const float4 wv = wreg[1][kk];
                const float va = ha[kk], vb = hb[kk];
                acc0.x += wv.x * va; acc0.y += wv.y * va;
                acc0.z += wv.z * va; acc0.w += wv.w * va;
                acc1.x += wv.x * vb; acc1.y += wv.y * vb;
                acc1.z += wv.z * vb; acc1.w += wv.w * vb;
            }
        }

        // ---- cross-warp reduction (both planes) + tanh + publish ----
        *(float4*)&sacc[0][w * 128 + lane * 4] = acc0;
        *(float4*)&sacc[1][w * 128 + lane * 4] = acc1;
        __syncthreads();
        {
            float s = zv;
            const float* plane = &sacc[pb][0];
#pragma unroll
            for (int ww = 0; ww < 8; ww++) s += plane[ww * 128 + pcol];
            const float hv = tanhf(s);
            sh_h[pb][pcolabs] = hv;                                // own half for t+1
            if (t < LL - 1) st_remote_f32(p_rb[t & 1], hv);        // push to peer buf
            Out[((size_t)pbatch * LL + t) * HH + pcolabs] = hv;    // result (off chain)
        }
        __syncwarp();                                              // warp stores ordered
        if (t < LL - 1 && lane == 0)
            mbar_arrive_remote_release(p_mbar[t & 1]);             // RELEASE.CLUSTER
        zv = zv_next;
        __syncthreads();   // sh_h own halves ready for all warps' next phase 1
    }

    if (hfinal)
        hfinal[pbatch * HH + pcolabs] = sh_h[pb][pcolabs];

    cluster_sync();   // no CTA exits while peer stores may be in flight
}

// ---------------------------------------------------------------------------
extern "C" void kernel_launch(void* const* d_in, const int* in_sizes, int n_in,
                              void* d_out, int out_size) {
    const float* x  = (const float*)d_in[0];   // [B,L,H]
    const float* h0 = (const float*)d_in[1];   // [NL,B,H]
    const float* WI = (const float*)d_in[2];   // [NL,H,H]
    const float* BI = (const float*)d_in[3];   // [NL,H]
    const float* WH = (const float*)d_in[4];   // [NL,H,H]
    const float* BH = (const float*)d_in[5];   // [NL,H]
    float* out = (float*)d_out;

    float *gZ = nullptr, *gH0 = nullptr;
    cudaGetSymbolAddress((void**)&gZ, g_Z);
    cudaGetSymbolAddress((void**)&gH0, g_H0);

    const dim3 ggrid(BB * LL / 128, HH / 128);  // (1024, 2)

    const bool haveMain  = (out_size >= BLH);
    const bool haveFinal = (out_size >= BLH + 2 * BB * HH);
    float* out2 = haveMain ? out : gZ;
    float* hf0  = haveFinal ? (out + BLH) : (haveMain ? nullptr : out);
    float* hf1  = haveFinal ? (out + BLH + BB * HH)
                            : (haveMain ? nullptr : out + BB * HH);

    // Phase A: Z0 = X @ WI0 + BI0 + BH0
    gemm_bias<<<ggrid, 256>>>(x, WI, BI, BH, gZ);
    // Phase B: layer-0 recurrence (32 clusters x 2 CTAs, 2 batches each)
    rnn_pass2<<<BB, 256>>>(gZ, WH, h0, gH0, hf0);
    // Phase C: Z1 = H0 @ WI1 + BI1 + BH1
    gemm_bias<<<ggrid, 256>>>(gH0, WI + HH * HH, BI + HH, BH + HH, gZ);
    // Phase D: layer-1 recurrence -> output
    rnn_pass2<<<BB, 256>>>(gZ, WH + HH * HH, h0 + BB * HH, out2, hf1);
}

// round 11
// speedup vs baseline: 1.5321x; 1.0537x over previous
#include <cuda_runtime.h>
#include <math.h>
#include <cstdint>

#define BB 64
#define LL 2048
#define HH 256
#define BLH (BB*LL*HH)

// Scratch (device globals: allocation-free per harness rules)
__device__ float g_Z[BLH];     // input-transform term per (b,t,h)
__device__ float g_H0[BLH];    // layer-0 hidden states

// ---------------------------------------------------------------------------
// PTX helpers (R8-proven set)
__device__ __forceinline__ uint32_t s2u(const void* p) {
    uint32_t a;
    asm("{ .reg .u64 t; cvta.to.shared.u64 t, %1; cvt.u32.u64 %0, t; }"
        : "=r"(a) : "l"(p));
    return a;
}
__device__ __forceinline__ uint32_t mapa_u32(uint32_t addr, uint32_t rank) {
    uint32_t r;
    asm("mapa.shared::cluster.u32 %0, %1, %2;" : "=r"(r) : "r"(addr), "r"(rank));
    return r;
}
__device__ __forceinline__ void mbar_init(uint32_t mbar, uint32_t count) {
    asm volatile("mbarrier.init.shared::cta.b64 [%0], %1;" :: "r"(mbar), "r"(count) : "memory");
}
__device__ __forceinline__ void st_remote_f32(uint32_t raddr, float v) {
    asm volatile("st.shared::cluster.f32 [%0], %1;" :: "r"(raddr), "f"(v) : "memory");
}
// Cluster-scope release arrive on peer's mbarrier (orders prior cluster stores).
__device__ __forceinline__ void mbar_arrive_remote_release(uint32_t raddr) {
    asm volatile("mbarrier.arrive.release.cluster.shared::cluster.b64 _, [%0];"
                 :: "r"(raddr) : "memory");
}
__device__ __forceinline__ void mbar_wait_parity(uint32_t mbar, uint32_t parity) {
    uint32_t done;
    asm volatile(
        "{\n\t.reg .pred p;\n\t"
        "mbarrier.try_wait.parity.acquire.cluster.shared::cta.b64 p, [%1], %2;\n\t"
        "selp.b32 %0, 1, 0, p;\n\t}"
        : "=r"(done) : "r"(mbar), "r"(parity) : "memory");
    if (!done) {
        asm volatile(
            "{\n\t.reg .pred P1;\n\t"
            "WL_%=:\n\t"
            "mbarrier.try_wait.parity.acquire.cluster.shared::cta.b64 P1, [%0], %1, 0x989680;\n\t"
            "@P1 bra.uni WD_%=;\n\t"
            "bra.uni WL_%=;\n\t"
            "WD_%=:\n\t}"
            :: "r"(mbar), "r"(parity) : "memory");
    }
}
__device__ __forceinline__ void cluster_sync() {
    asm volatile("barrier.cluster.arrive.aligned;" ::: "memory");
    asm volatile("barrier.cluster.wait.aligned;" ::: "memory");
}

// ---------------------------------------------------------------------------
// GEMM + bias (R8-proven scalar version): Out[r][j] = In[r]·W[:,j] + bi[j] + bh[j]
// M = 131072, N = K = 256. Tile 128x128x8, 256 threads, 8x8/thread.
__global__ __launch_bounds__(256) void gemm_bias(
        const float* __restrict__ In, const float* __restrict__ W,
        const float* __restrict__ bi, const float* __restrict__ bh,
        float* __restrict__ Out)
{
    __shared__ float As[8][128];
    __shared__ float Bs[8][128];
    const int tid  = threadIdx.x;
    const int mblk = blockIdx.x * 128;
    const int nblk = blockIdx.y * 128;
    const int tx = tid & 15, ty = tid >> 4;

    const int ar = tid >> 1;
    const int ak = (tid & 1) * 4;
    const int bk = tid >> 5;
    const int bc = (tid & 31) * 4;

    const float* Arow = In + (size_t)(mblk + ar) * HH;
    float4 a_next = *(const float4*)(Arow + ak);
    float4 b_next = *(const float4*)(W + (size_t)bk * HH + nblk + bc);

    float acc[8][8];
#pragma unroll
    for (int i = 0; i < 8; i++)
#pragma unroll
        for (int j = 0; j < 8; j++) acc[i][j] = 0.f;

    for (int kt = 0; kt < 32; kt++) {
        As[ak + 0][ar] = a_next.x;
        As[ak + 1][ar] = a_next.y;
        As[ak + 2][ar] = a_next.z;
        As[ak + 3][ar] = a_next.w;
        *(float4*)&Bs[bk][bc] = b_next;
        __syncthreads();
        if (kt < 31) {
            a_next = *(const float4*)(Arow + (kt + 1) * 8 + ak);
            b_next = *(const float4*)(W + (size_t)((kt + 1) * 8 + bk) * HH + nblk + bc);
        }
#pragma unroll
        for (int kk = 0; kk < 8; kk++) {
            float a[8], b[8];
            *(float4*)&a[0] = *(const float4*)&As[kk][ty * 8];
            *(float4*)&a[4] = *(const float4*)&As[kk][ty * 8 + 4];
            *(float4*)&b[0] = *(const float4*)&Bs[kk][tx * 8];
            *(float4*)&b[4] = *(const float4*)&Bs[kk][tx * 8 + 4];
#pragma unroll
            for (int i = 0; i < 8; i++)
#pragma unroll
                for (int j = 0; j < 8; j++) acc[i][j] += a[i] * b[j];
        }
        __syncthreads();
    }

#pragma unroll
    for (int i = 0; i < 8; i++) {
        const size_t r = (size_t)(mblk + ty * 8 + i);
#pragma unroll
        for (int j = 0; j < 8; j += 4) {
            const int c = nblk + tx * 8 + j;
            float4 v;
            v.x = acc[i][j + 0] + bi[c + 0] + bh[c + 0];
            v.y = acc[i][j + 1] + bi[c + 1] + bh[c + 1];
            v.z = acc[i][j + 2] + bi[c + 2] + bh[c + 2];
            v.w = acc[i][j + 3] + bi[c + 3] + bh[c + 3];
            *(float4*)(Out + r * HH + c) = v;
        }
    }
}

// ---------------------------------------------------------------------------
// Recurrence pass v3: warp-private columns + scalar FFMA + shfl reduction.
//   Cluster of 2 CTAs per batch; CTA rank r owns cols [r*128,+128).
//   Warp w owns cols [w*16,+16); lane l -> col (l&15), k-quarter (l>>4).
//   Each thread: 64 scalar FFMA over its own-half k-quarter (BEFORE the
//   wait), 64 over the peer-half k-quarter (after), 4 independent acc
//   chains. shfl_xor(16) merges the two k-quarters -> full dot product in
//   lanes 0-15. No smem reduction, ONE __syncthreads per step.
//   Exchange (R8-proven): remote stores into peer's double-buffered recvbuf
//   + one release.cluster arrive per warp (count=8); acquire try_wait.
__global__ __launch_bounds__(256, 1) __cluster_dims__(2, 1, 1)
void rnn_pass(
        const float* __restrict__ Z,    // [B,L,H]
        const float* __restrict__ Wh,   // [H,H]
        const float* __restrict__ h0,   // [B,H]
        float* __restrict__ Out,        // [B,L,H]
        float* __restrict__ hfinal)     // [B,H] or null
{
    const int b     = blockIdx.x >> 1;
    const int half  = blockIdx.x & 1;            // == cluster rank
    const int jbase = half << 7;
    const int peerbase = 128 - jbase;
    const int tid  = threadIdx.x;
    const int w    = tid >> 5;
    const int lane = tid & 31;
    const int cl   = (w << 4) + (lane & 15);     // col within own block (0..127)
    const int kq   = lane >> 4;                  // k-quarter selector (0/1)
    const int colabs = jbase + cl;

    __shared__ float sh_h[256];                  // own half live; peer half only at t=0
    __shared__ float recvbuf[2][128];            // peer halves, double-buffered
    __shared__ uint64_t mbar[2];

    const uint32_t mbar0 = s2u(&mbar[0]);
    const uint32_t mbar1 = s2u(&mbar[1]);
    const uint32_t rb0   = s2u(&recvbuf[0][0]);
    const uint32_t rb1   = s2u(&recvbuf[1][0]);
    const uint32_t prank = (uint32_t)(half ^ 1);
    const uint32_t p_rb[2]   = { mapa_u32(rb0 + (uint32_t)cl * 4u, prank),
                                 mapa_u32(rb1 + (uint32_t)cl * 4u, prank) };
    const uint32_t p_mbar[2] = { mapa_u32(mbar0, prank), mapa_u32(mbar1, prank) };
    const uint32_t l_mbar[2] = { mbar0, mbar1 };

    if (tid == 0) { mbar_init(mbar0, 8); mbar_init(mbar1, 8); }   // 8 producer warps

    // Weights: 64 scalar regs per phase for this thread's (col, k-quarter).
    float wown[64], wpeer[64];
#pragma unroll
    for (int i = 0; i < 64; i++)
        wown[i] = Wh[(size_t)(jbase + kq * 64 + i) * HH + colabs];
#pragma unroll
    for (int i = 0; i < 64; i++)
        wpeer[i] = Wh[(size_t)(peerbase + kq * 64 + i) * HH + colabs];

    sh_h[tid] = h0[b * HH + tid];
    __syncthreads();
    cluster_sync();   // mbarrier init visible cluster-wide before any remote arrive

    // Z prefetch (one step ahead); publishing lanes (0-15) only.
    float zv = (lane < 16) ? Z[((size_t)b * LL + 0) * HH + colabs] : 0.f;

    for (int t = 0; t < LL; t++) {
        float zv_next = 0.f;
        if (t + 1 < LL && lane < 16)
            zv_next = Z[((size_t)b * LL + (t + 1)) * HH + colabs];

        float acc0 = 0.f, acc1 = 0.f, acc2 = 0.f, acc3 = 0.f;

        // ---- phase 1: own k-quarter (local, no wait): 64 FFMA ----
        {
            const float4* h4 = (const float4*)(sh_h + jbase + kq * 64);
#pragma unroll
            for (int m = 0; m < 16; m++) {
                const float4 hv4 = h4[m];
                acc0 += wown[4 * m + 0] * hv4.x;
                acc1 += wown[4 * m + 1] * hv4.y;
                acc2 += wown[4 * m + 2] * hv4.z;
                acc3 += wown[4 * m + 3] * hv4.w;
            }
        }

        // ---- wait for peer half of h_{t-1} ----
        const float4* s4;
        if (t > 0) {
            mbar_wait_parity(l_mbar[(t - 1) & 1], ((t - 1) >> 1) & 1);
            s4 = (const float4*)(&recvbuf[(t - 1) & 1][kq * 64]);
        } else {
            s4 = (const float4*)(sh_h + peerbase + kq * 64);
        }

        // ---- phase 2: peer k-quarter: 64 FFMA ----
        {
#pragma unroll
            for (int m = 0; m < 16; m++) {
                const float4 hv4 = s4[m];
                acc0 += wpeer[4 * m + 0] * hv4.x;
                acc1 += wpeer[4 * m + 1] * hv4.y;
                acc2 += wpeer[4 * m + 2] * hv4.z;
                acc3 += wpeer[4 * m + 3] * hv4.w;
            }
        }

        // ---- merge quarters via shfl + tanh + publish ----
        float s = (acc0 + acc1) + (acc2 + acc3);
        s += __shfl_xor_sync(0xffffffffu, s, 16);
        if (lane < 16) {
            const float hv = tanhf(s + zv);
            sh_h[colabs] = hv;                                    // own half for t+1
            if (t < LL - 1) st_remote_f32(p_rb[t & 1], hv);       // push to peer buf
            Out[((size_t)b * LL + t) * HH + colabs] = hv;         // result (off chain)
        }
        __syncwarp();                                             // warp stores ordered
        if (t < LL - 1 && lane == 0)
            mbar_arrive_remote_release(p_mbar[t & 1]);            // RELEASE.CLUSTER
        zv = zv_next;
        __syncthreads();   // sh_h own half ready for all warps' next phase 1
    }

    if (hfinal && lane < 16)
        hfinal[b * HH + colabs] = sh_h[colabs];

    cluster_sync();   // no CTA exits while peer stores may be in flight
}

// ---------------------------------------------------------------------------
extern "C" void kernel_launch(void* const* d_in, const int* in_sizes, int n_in,
                              void* d_out, int out_size) {
    const float* x  = (const float*)d_in[0];   // [B,L,H]
    const float* h0 = (const float*)d_in[1];   // [NL,B,H]
    const float* WI = (const float*)d_in[2];   // [NL,H,H]
    const float* BI = (const float*)d_in[3];   // [NL,H]
    const float* WH = (const float*)d_in[4];   // [NL,H,H]
    const float* BH = (const float*)d_in[5];   // [NL,H]
    float* out = (float*)d_out;

    float *gZ = nullptr, *gH0 = nullptr;
    cudaGetSymbolAddress((void**)&gZ, g_Z);
    cudaGetSymbolAddress((void**)&gH0, g_H0);

    const dim3 ggrid(BB * LL / 128, HH / 128);  // (1024, 2)

    const bool haveMain  = (out_size >= BLH);
    const bool haveFinal = (out_size >= BLH + 2 * BB * HH);
    float* out2 = haveMain ? out : gZ;
    float* hf0  = haveFinal ? (out + BLH) : (haveMain ? nullptr : out);
    float* hf1  = haveFinal ? (out + BLH + BB * HH)
                            : (haveMain ? nullptr : out + BB * HH);

    // Phase A: Z0 = X @ WI0 + BI0 + BH0
    gemm_bias<<<ggrid, 256>>>(x, WI, BI, BH, gZ);
    // Phase B: layer-0 recurrence (64 clusters x 2 CTAs)
    rnn_pass<<<2 * BB, 256>>>(gZ, WH, h0, gH0, hf0);
    // Phase C: Z1 = H0 @ WI1 + BI1 + BH1
    gemm_bias<<<ggrid, 256>>>(gH0, WI + HH * HH, BI + HH, BH + HH, gZ);
    // Phase D: layer-1 recurrence -> output
    rnn_pass<<<2 * BB, 256>>>(gZ, WH + HH * HH, h0 + BB * HH, out2, hf1);
}

// round 12
// speedup vs baseline: 2.5986x; 1.6960x over previous
#include <cuda_runtime.h>
#include <math.h>
#include <cstdint>

#define BB 64
#define LL 2048
#define HH 256
#define BLH (BB*LL*HH)

// Scratch (device globals: allocation-free per harness rules)
__device__ float g_Z[BLH];     // input-transform term per (b,t,h)
__device__ float g_H0[BLH];    // layer-0 hidden states

// ---------------------------------------------------------------------------
// PTX helpers
__device__ __forceinline__ uint32_t s2u(const void* p) {
    uint32_t a;
    asm("{ .reg .u64 t; cvta.to.shared.u64 t, %1; cvt.u32.u64 %0, t; }"
        : "=r"(a) : "l"(p));
    return a;
}
__device__ __forceinline__ uint32_t mapa_u32(uint32_t addr, uint32_t rank) {
    uint32_t r;
    asm("mapa.shared::cluster.u32 %0, %1, %2;" : "=r"(r) : "r"(addr), "r"(rank));
    return r;
}
__device__ __forceinline__ void mbar_init(uint32_t mbar, uint32_t count) {
    asm volatile("mbarrier.init.shared::cta.b64 [%0], %1;" :: "r"(mbar), "r"(count) : "memory");
}
__device__ __forceinline__ void mbar_expect_tx(uint32_t mbar, uint32_t bytes) {
    asm volatile("mbarrier.arrive.expect_tx.shared::cta.b64 _, [%0], %1;"
                 :: "r"(mbar), "r"(bytes) : "memory");
}
// Async remote store into peer CTA's SMEM; data + completion travel together,
// completion counted (in bytes) on the peer's mbarrier. No fence, no arrive.
__device__ __forceinline__ void st_async_u32(uint32_t raddr, uint32_t v, uint32_t rmbar) {
    asm volatile("st.async.shared::cluster.mbarrier::complete_tx::bytes.b32 [%0], %1, [%2];"
                 :: "r"(raddr), "r"(v), "r"(rmbar) : "memory");
}
__device__ __forceinline__ void mbar_wait_parity(uint32_t mbar, uint32_t parity) {
    uint32_t done;
    asm volatile(
        "{\n\t.reg .pred p;\n\t"
        "mbarrier.try_wait.parity.acquire.cluster.shared::cta.b64 p, [%1], %2;\n\t"
        "selp.b32 %0, 1, 0, p;\n\t}"
        : "=r"(done) : "r"(mbar), "r"(parity) : "memory");
    if (!done) {
        asm volatile(
            "{\n\t.reg .pred P1;\n\t"
            "WL_%=:\n\t"
            "mbarrier.try_wait.parity.acquire.cluster.shared::cta.b64 P1, [%0], %1, 0x989680;\n\t"
            "@P1 bra.uni WD_%=;\n\t"
            "bra.uni WL_%=;\n\t"
            "WD_%=:\n\t}"
            :: "r"(mbar), "r"(parity) : "memory");
    }
}
__device__ __forceinline__ void cluster_sync() {
    asm volatile("barrier.cluster.arrive.aligned;" ::: "memory");
    asm volatile("barrier.cluster.wait.aligned;" ::: "memory");
}

// Branch-free fast tanh: 1 - 2/(exp(2x)+1). Handles +-inf saturation
// correctly (exp->inf => 1; exp->0 => -1). ~1e-6 rel err, 2 MUFU ops.
__device__ __forceinline__ float tanh_fast(float x) {
    const float e = __expf(2.0f * x);
    return 1.0f - __fdividef(2.0f, e + 1.0f);
}

// ---------------------------------------------------------------------------
// GEMM + bias (R8-proven): Out[r][j] = In[r]·W[:,j] + bi[j] + bh[j]
// M = 131072, N = K = 256. Tile 128x128x8, 256 threads, 8x8/thread.
__global__ __launch_bounds__(256) void gemm_bias(
        const float* __restrict__ In, const float* __restrict__ W,
        const float* __restrict__ bi, const float* __restrict__ bh,
        float* __restrict__ Out)
{
    __shared__ float As[8][128];
    __shared__ float Bs[8][128];
    const int tid  = threadIdx.x;
    const int mblk = blockIdx.x * 128;
    const int nblk = blockIdx.y * 128;
    const int tx = tid & 15, ty = tid >> 4;

    const int ar = tid >> 1;
    const int ak = (tid & 1) * 4;
    const int bk = tid >> 5;
    const int bc = (tid & 31) * 4;

    const float* Arow = In + (size_t)(mblk + ar) * HH;
    float4 a_next = *(const float4*)(Arow + ak);
    float4 b_next = *(const float4*)(W + (size_t)bk * HH + nblk + bc);

    float acc[8][8];
#pragma unroll
    for (int i = 0; i < 8; i++)
#pragma unroll
        for (int j = 0; j < 8; j++) acc[i][j] = 0.f;

    for (int kt = 0; kt < 32; kt++) {
        As[ak + 0][ar] = a_next.x;
        As[ak + 1][ar] = a_next.y;
        As[ak + 2][ar] = a_next.z;
        As[ak + 3][ar] = a_next.w;
        *(float4*)&Bs[bk][bc] = b_next;
        __syncthreads();
        if (kt < 31) {
            a_next = *(const float4*)(Arow + (kt + 1) * 8 + ak);
            b_next = *(const float4*)(W + (size_t)((kt + 1) * 8 + bk) * HH + nblk + bc);
        }
#pragma unroll
        for (int kk = 0; kk < 8; kk++) {
            float a[8], b[8];
            *(float4*)&a[0] = *(const float4*)&As[kk][ty * 8];
            *(float4*)&a[4] = *(const float4*)&As[kk][ty * 8 + 4];
            *(float4*)&b[0] = *(const float4*)&Bs[kk][tx * 8];
            *(float4*)&b[4] = *(const float4*)&Bs[kk][tx * 8 + 4];
#pragma unroll
            for (int i = 0; i < 8; i++)
#pragma unroll
                for (int j = 0; j < 8; j++) acc[i][j] += a[i] * b[j];
        }
        __syncthreads();
    }

#pragma unroll
    for (int i = 0; i < 8; i++) {
        const size_t r = (size_t)(mblk + ty * 8 + i);
#pragma unroll
        for (int j = 0; j < 8; j += 4) {
            const int c = nblk + tx * 8 + j;
            float4 v;
            v.x = acc[i][j + 0] + bi[c + 0] + bh[c + 0];
            v.y = acc[i][j + 1] + bi[c + 1] + bh[c + 1];
            v.z = acc[i][j + 2] + bi[c + 2] + bh[c + 2];
            v.w = acc[i][j + 3] + bi[c + 3] + bh[c + 3];
            *(float4*)(Out + r * HH + c) = v;
        }
    }
}

// ---------------------------------------------------------------------------
// Recurrence pass (R8 structure; exchange via st.async/complete_tx; fast tanh).
// Cluster of 2 CTAs per batch; CTA rank r owns cols [r*128,+128); 256x128 WH
// slice in registers. Per step each of 128 publishing threads does ONE
// st.async of its h value into the peer's double-buffered recvbuf; the
// peer's mbarrier completes on 512 tx bytes. expect_tx sequencing is
// race-free by construction: expects for data 0/1 are posted before
// cluster_sync; the expect for data t+1 is posted before our send of h_t,
// which the peer must receive before it can produce data t+1.
__global__ __launch_bounds__(256, 1) __cluster_dims__(2, 1, 1)
void rnn_pass(
        const float* __restrict__ Z,    // [B,L,H]
        const float* __restrict__ Wh,   // [H,H]
        const float* __restrict__ h0,   // [B,H]
        float* __restrict__ Out,        // [B,L,H]
        float* __restrict__ hfinal)     // [B,H] or null
{
    const int b     = blockIdx.x >> 1;
    const int half  = blockIdx.x & 1;            // == cluster rank
    const int jbase = half << 7;
    const int peerbase = 128 - jbase;
    const int tid  = threadIdx.x;
    const int w    = tid >> 5;
    const int lane = tid & 31;
    const int j0   = jbase + lane * 4;

    __shared__ float sh_h[256];                  // own half live; peer half only at t=0
    __shared__ float recvbuf[2][128];            // peer halves, double-buffered
    __shared__ float sacc[8 * 128];
    __shared__ uint64_t mbar[2];

    const uint32_t mbar0 = s2u(&mbar[0]);
    const uint32_t mbar1 = s2u(&mbar[1]);
    const uint32_t rb0   = s2u(&recvbuf[0][0]);
    const uint32_t rb1   = s2u(&recvbuf[1][0]);
    const uint32_t prank = (uint32_t)(half ^ 1);
    const uint32_t p_rb[2]   = { mapa_u32(rb0 + (uint32_t)tid * 4u, prank),
                                 mapa_u32(rb1 + (uint32_t)tid * 4u, prank) };
    const uint32_t p_mbar[2] = { mapa_u32(mbar0, prank), mapa_u32(mbar1, prank) };
    const uint32_t l_mbar[2] = { mbar0, mbar1 };

    if (tid == 0) {
        mbar_init(mbar0, 1);                 // 1 arrival = the expect_tx itself
        mbar_init(mbar1, 1);
        mbar_expect_tx(mbar0, 512);          // data 0 (arrives into buf 0)
        mbar_expect_tx(mbar1, 512);          // data 1 (arrives into buf 1)
    }

    // Weight slice: wreg[0] = own k-half rows, wreg[1] = peer k-half rows.
    float4 wreg[2][16];
    const int kb0 = jbase, kb1 = peerbase;
#pragma unroll
    for (int kk = 0; kk < 16; kk++)
        wreg[0][kk] = *(const float4*)(Wh + (size_t)(kb0 + w * 16 + kk) * HH + j0);
#pragma unroll
    for (int kk = 0; kk < 16; kk++)
        wreg[1][kk] = *(const float4*)(Wh + (size_t)(kb1 + w * 16 + kk) * HH + j0);

    sh_h[tid] = h0[b * HH + tid];
    __syncthreads();
    cluster_sync();   // both CTAs' mbarrier init + initial expects visible before any send

    const float4* shh4 = (const float4*)sh_h;

    // Z prefetch (one step ahead)
    float zv = (tid < 128) ? Z[((size_t)b * LL + 0) * HH + jbase + tid] : 0.f;

    for (int t = 0; t < LL; t++) {
        // Prefetch next step's Z while we compute this one.
        float zv_next = 0.f;
        if (t + 1 < LL && tid < 128)
            zv_next = Z[((size_t)b * LL + (t + 1)) * HH + jbase + tid];

        float4 acc = make_float4(0.f, 0.f, 0.f, 0.f);

        // ---- phase 1: own k-half (local, no wait) ----
        {
            float hbuf[16];
            const int b4 = (kb0 + w * 16) >> 2;
            *(float4*)&hbuf[0]  = shh4[b4 + 0];
            *(float4*)&hbuf[4]  = shh4[b4 + 1];
            *(float4*)&hbuf[8]  = shh4[b4 + 2];
            *(float4*)&hbuf[12] = shh4[b4 + 3];
#pragma unroll
            for (int kk = 0; kk < 16; kk++) {
                const float hv = hbuf[kk];
                acc.x += wreg[0][kk].x * hv;
                acc.y += wreg[0][kk].y * hv;
                acc.z += wreg[0][kk].z * hv;
                acc.w += wreg[0][kk].w * hv;
            }
        }

        // ---- wait for peer half of h_{t-1}; then pre-post expect for data t+1 ----
        const float4* src;
        if (t > 0) {
            mbar_wait_parity(l_mbar[(t - 1) & 1], ((t - 1) >> 1) & 1);
            // Re-arm this buffer's mbarrier for data t+1. Safe: peer cannot
            // send data t+1 until it has received our h_t, which we send
            // AFTER this point (program order).
            if (t <= LL - 3 && tid == 0)
                mbar_expect_tx(l_mbar[(t - 1) & 1], 512);
            src = (const float4*)&recvbuf[(t - 1) & 1][0];   // indexed by k - peerbase
        } else {
            src = (const float4*)&sh_h[kb1];                  // h0 peer half
        }

        // ---- phase 2: peer k-half ----
        {
            float hbuf[16];
            const int b4 = (w * 16) >> 2;
            *(float4*)&hbuf[0]  = src[b4 + 0];
            *(float4*)&hbuf[4]  = src[b4 + 1];
            *(float4*)&hbuf[8]  = src[b4 + 2];
            *(float4*)&hbuf[12] = src[b4 + 3];
#pragma unroll
            for (int kk = 0; kk < 16; kk++) {
                const float hv = hbuf[kk];
                acc.x += wreg[1][kk].x * hv;
                acc.y += wreg[1][kk].y * hv;
                acc.z += wreg[1][kk].z * hv;
                acc.w += wreg[1][kk].w * hv;
            }
        }

        // ---- cross-warp reduction + tanh + publish ----
        *(float4*)&sacc[w * 128 + lane * 4] = acc;
        __syncthreads();
        if (tid < 128) {
            float s = zv;
#pragma unroll
            for (int ww = 0; ww < 8; ww++) s += sacc[ww * 128 + tid];
            const float hv = tanh_fast(s);
            sh_h[jbase + tid] = hv;                                 // own half for t+1
            if (t < LL - 1)
                st_async_u32(p_rb[t & 1], __float_as_uint(hv),
                             p_mbar[t & 1]);                        // async push+complete
            Out[((size_t)b * LL + t) * HH + jbase + tid] = hv;      // result (off chain)
        }
        zv = zv_next;
        __syncthreads();   // protects sh_h own-half and sacc reuse
    }

    if (hfinal && tid < 128)
        hfinal[b * HH + jbase + tid] = sh_h[jbase + tid];

    cluster_sync();   // no CTA exits while peer stores may be in flight
}

// ---------------------------------------------------------------------------
extern "C" void kernel_launch(void* const* d_in, const int* in_sizes, int n_in,
                              void* d_out, int out_size) {
    const float* x  = (const float*)d_in[0];   // [B,L,H]
    const float* h0 = (const float*)d_in[1];   // [NL,B,H]
    const float* WI = (const float*)d_in[2];   // [NL,H,H]
    const float* BI = (const float*)d_in[3];   // [NL,H]
    const float* WH = (const float*)d_in[4];   // [NL,H,H]
    const float* BH = (const float*)d_in[5];   // [NL,H]
    float* out = (float*)d_out;

    float *gZ = nullptr, *gH0 = nullptr;
    cudaGetSymbolAddress((void**)&gZ, g_Z);
    cudaGetSymbolAddress((void**)&gH0, g_H0);

    const dim3 ggrid(BB * LL / 128, HH / 128);  // (1024, 2)

    const bool haveMain  = (out_size >= BLH);
    const bool haveFinal = (out_size >= BLH + 2 * BB * HH);
    float* out2 = haveMain ? out : gZ;
    float* hf0  = haveFinal ? (out + BLH) : (haveMain ? nullptr : out);
    float* hf1  = haveFinal ? (out + BLH + BB * HH)
                            : (haveMain ? nullptr : out + BB * HH);

    // Phase A: Z0 = X @ WI0 + BI0 + BH0
    gemm_bias<<<ggrid, 256>>>(x, WI, BI, BH, gZ);
    // Phase B: layer-0 recurrence (64 clusters x 2 CTAs)
    rnn_pass<<<2 * BB, 256>>>(gZ, WH, h0, gH0, hf0);
    // Phase C: Z1 = H0 @ WI1 + BI1 + BH1
    gemm_bias<<<ggrid, 256>>>(gH0, WI + HH * HH, BI + HH, BH + HH, gZ);
    // Phase D: layer-1 recurrence -> output
    rnn_pass<<<2 * BB, 256>>>(gZ, WH + HH * HH, h0 + BB * HH, out2, hf1);
}